// round 4
// baseline (speedup 1.0000x reference)
#include <cuda_runtime.h>
#include <math.h>

#define NN   50000
#define NE   800000
#define NF   64
#define NRBF 10
#define NG   512
#define NH   64

// ---------------- scratch (device globals) ----------------
__device__ float4 g_x4[NN * 16];       // node features
__device__ float4 g_h4[NN * 16];       // pre-message transform
__device__ float4 g_agg4[NN * 16];     // aggregation result (exclusive writes)
__device__ float4 g_gsum4[NG * 16];    // per-graph sums
__device__ float  g_gcnt[NG];          // per-graph counts
__device__ int    g_deg[NN];           // in-degree histogram
__device__ int    g_rowptr[NN + 1];    // CSR row pointers (by dst)
__device__ int    g_cursor[NN];        // scatter cursors
__device__ int    g_csr_src[NE + 16];  // src ids, dst-sorted
__device__ float  g_csr_dist[NE + 16]; // distances, dst-sorted

// ---------------- helpers ----------------
__device__ __forceinline__ void red_add_v4(float* p, float4 v) {
    asm volatile("red.global.add.v4.f32 [%0], {%1,%2,%3,%4};"
                 :: "l"(p), "f"(v.x), "f"(v.y), "f"(v.z), "f"(v.w) : "memory");
}
__device__ __forceinline__ void red_add_f(float* p, float v) {
    asm volatile("red.global.add.f32 [%0], %1;" :: "l"(p), "f"(v) : "memory");
}
__device__ __forceinline__ unsigned long long pack2(float x, float y) {
    unsigned long long r;
    asm("mov.b64 %0, {%1,%2};" : "=l"(r) : "f"(x), "f"(y));
    return r;
}
__device__ __forceinline__ void fma2(unsigned long long& d, unsigned long long a, unsigned long long b) {
    asm("fma.rn.f32x2 %0, %1, %2, %3;" : "=l"(d) : "l"(a), "l"(b), "l"(d));
}
__device__ __forceinline__ float2 unpack2(unsigned long long v) {
    float2 f;
    asm("mov.b64 {%0,%1}, %2;" : "=f"(f.x), "=f"(f.y) : "l"(v));
    return f;
}
__device__ __forceinline__ float4 f4fma(float s, float4 w, float4 a) {
    return make_float4(fmaf(s, w.x, a.x), fmaf(s, w.y, a.y),
                       fmaf(s, w.z, a.z), fmaf(s, w.w, a.w));
}
__device__ __forceinline__ float sp(float x) {   // stable softplus
    return fmaxf(x, 0.0f) + log1pf(expf(-fabsf(x)));
}

// ---------------- CSR build ----------------
__global__ void k_zero() {
    int t = blockIdx.x * blockDim.x + threadIdx.x;
    if (t < NN) g_deg[t] = 0;
    if (t < NG * 16) g_gsum4[t] = make_float4(0.f, 0.f, 0.f, 0.f);
    if (t < NG) g_gcnt[t] = 0.0f;
}
__global__ void k_hist(const int* __restrict__ dst) {
    int e = blockIdx.x * blockDim.x + threadIdx.x;
    if (e < NE) atomicAdd(&g_deg[dst[e]], 1);
}
__global__ void k_scan() {
    __shared__ int sums[1024];
    int t = threadIdx.x;
    const int CH = (NN + 1023) / 1024;
    int base = t * CH;
    int s = 0;
    for (int i = 0; i < CH; i++) {
        int idx = base + i;
        if (idx < NN) s += g_deg[idx];
    }
    sums[t] = s;
    __syncthreads();
    for (int off = 1; off < 1024; off <<= 1) {
        int v = (t >= off) ? sums[t - off] : 0;
        __syncthreads();
        sums[t] += v;
        __syncthreads();
    }
    int run = (t == 0) ? 0 : sums[t - 1];
    for (int i = 0; i < CH; i++) {
        int idx = base + i;
        if (idx < NN) {
            g_rowptr[idx] = run;
            g_cursor[idx] = run;
            run += g_deg[idx];
        }
    }
    if (t == 1023) g_rowptr[NN] = NE;
}
__global__ void k_scatter(const int* __restrict__ src, const int* __restrict__ dst,
                          const float* __restrict__ ea) {
    int e = blockIdx.x * blockDim.x + threadIdx.x;
    if (e >= NE) return;
    int pos = atomicAdd(&g_cursor[dst[e]], 1);
    g_csr_src[pos]  = src[e];
    g_csr_dist[pos] = ea[e];
}

// ---------------- node GEMM: 64 rows/block, 128 thr, 4 rows x 8 cols/thread ----------------
// mode 0: g_h = in @ W + b   (if ids != null: in = emb[ids], also writes g_x)
// mode 1: g_x = softplus(g_x + g_agg @ W + b)
// mode 2: like 1, result goes straight to graph pool
__global__ __launch_bounds__(128) void k_node_gemm(
        const float* __restrict__ W, const float* __restrict__ b, int mode,
        const int* __restrict__ ids, const float4* __restrict__ emb4,
        const int* __restrict__ batch) {
    __shared__ float4 Ws4[NF * 16];       // W[64][64] as float4
    __shared__ float4 xs4[64 * 17];       // 64 input rows, padded
    __shared__ float  bs[NF];

    int t = threadIdx.x;
    const float4* W4 = (const float4*)W;
#pragma unroll
    for (int i = 0; i < 8; i++) Ws4[t + 128 * i] = W4[t + 128 * i];
    if (t < NF) bs[t] = b[t];

    int rowbase = blockIdx.x * 64;
    const float4* in4 = (mode == 0) ? g_x4 : g_agg4;

#pragma unroll
    for (int i = 0; i < 8; i++) {
        int idx = t + 128 * i;              // [0,1024)
        int lr = idx >> 4, c = idx & 15;
        int row = rowbase + lr;
        if (row < NN) {
            float4 v;
            if (ids) {
                v = emb4[(size_t)ids[row] * 16 + c];
                g_x4[(size_t)row * 16 + c] = v;
            } else {
                v = in4[(size_t)row * 16 + c];
            }
            xs4[lr * 17 + c] = v;
        }
    }
    __syncthreads();

    int cg = t & 7;               // cols cg*8 .. cg*8+7
    int rl = t >> 3;              // 0..15; rows rl + 16*i

    unsigned long long a[4][4];
    {
        int cb = cg * 8;
        unsigned long long b0 = pack2(bs[cb + 0], bs[cb + 1]);
        unsigned long long b1 = pack2(bs[cb + 2], bs[cb + 3]);
        unsigned long long b2 = pack2(bs[cb + 4], bs[cb + 5]);
        unsigned long long b3 = pack2(bs[cb + 6], bs[cb + 7]);
#pragma unroll
        for (int i = 0; i < 4; i++) { a[i][0] = b0; a[i][1] = b1; a[i][2] = b2; a[i][3] = b3; }
    }

#pragma unroll 4
    for (int k4 = 0; k4 < 16; k4++) {
        float4 xv[4];
#pragma unroll
        for (int i = 0; i < 4; i++) xv[i] = xs4[(rl + 16 * i) * 17 + k4];
#pragma unroll
        for (int sub = 0; sub < 4; sub++) {
            int k = k4 * 4 + sub;
            const ulonglong2* wp = (const ulonglong2*)(Ws4 + k * 16 + cg * 2);
            ulonglong2 wA = wp[0];
            ulonglong2 wB = wp[1];
#pragma unroll
            for (int i = 0; i < 4; i++) {
                float xk = (sub == 0) ? xv[i].x : (sub == 1) ? xv[i].y : (sub == 2) ? xv[i].z : xv[i].w;
                unsigned long long s = pack2(xk, xk);
                fma2(a[i][0], s, wA.x);
                fma2(a[i][1], s, wA.y);
                fma2(a[i][2], s, wB.x);
                fma2(a[i][3], s, wB.y);
            }
        }
    }

#pragma unroll
    for (int i = 0; i < 4; i++) {
        int row = rowbase + rl + 16 * i;
        if (row >= NN) continue;
        float2 p0 = unpack2(a[i][0]), p1 = unpack2(a[i][1]);
        float2 p2 = unpack2(a[i][2]), p3 = unpack2(a[i][3]);
        float4 r0 = make_float4(p0.x, p0.y, p1.x, p1.y);
        float4 r1 = make_float4(p2.x, p2.y, p3.x, p3.y);
        size_t o = (size_t)row * 16 + cg * 2;
        if (mode == 0) {
            g_h4[o]     = r0;
            g_h4[o + 1] = r1;
        } else {
            float4 x0 = g_x4[o], x1 = g_x4[o + 1];
            x0 = make_float4(sp(x0.x + r0.x), sp(x0.y + r0.y), sp(x0.z + r0.z), sp(x0.w + r0.w));
            x1 = make_float4(sp(x1.x + r1.x), sp(x1.y + r1.y), sp(x1.z + r1.z), sp(x1.w + r1.w));
            if (mode == 1) {
                g_x4[o]     = x0;
                g_x4[o + 1] = x1;
            } else {
                int bg = batch[row];
                red_add_v4((float*)(g_gsum4 + (size_t)bg * 16 + cg * 2), x0);
                red_add_v4((float*)(g_gsum4 + (size_t)bg * 16 + cg * 2 + 1), x1);
                if (cg == 0) red_add_f(&g_gcnt[bg], 1.0f);
            }
        }
    }
}

// ---------------- CSR edge kernel: 16-lane group per dst node, no atomics ----------------
__global__ void k_edge_csr(const float* __restrict__ We, const float* __restrict__ be) {
    __shared__ float4 Wf4[NRBF * 16];
    __shared__ float4 bef4[16];
    int t = threadIdx.x;
    if (t < NRBF * 16) Wf4[t] = ((const float4*)We)[t];
    if (t >= NRBF * 16 && t < NRBF * 16 + 16) bef4[t - NRBF * 16] = ((const float4*)be)[t - NRBF * 16];
    __syncthreads();

    int wid = t >> 5, lane = t & 31;
    int sub = lane >> 4;
    int sl  = lane & 15;
    unsigned mask = sub ? 0xFFFF0000u : 0x0000FFFFu;
    int srcbase = sub << 4;

    int node = blockIdx.x * 16 + wid * 2 + sub;
    if (node >= NN) return;

    int p   = g_rowptr[node];
    int end = g_rowptr[node + 1];

    float4 acc = make_float4(0.f, 0.f, 0.f, 0.f);

    if (p < end) {
        int   s_cur = g_csr_src[p];
        float d_cur = g_csr_dist[p];
        for (; p < end; p++) {
            int   s   = s_cur;
            float dist = d_cur;
            if (p + 1 < end) {                 // prefetch next edge
                s_cur = g_csr_src[p + 1];
                d_cur = g_csr_dist[p + 1];
            }
            // issue the gather early
            float4 hv = __ldg(g_h4 + (size_t)s * 16 + sl);

            float ev = 0.0f;
            if (sl < NRBF) {
                float tt = dist - 0.66666667f * (float)sl;
                ev = expf(-1.125f * tt * tt);
            }
            float4 f = bef4[sl];
#pragma unroll
            for (int r = 0; r < NRBF; r++) {
                float er = __shfl_sync(mask, ev, srcbase + r);
                f = f4fma(er, Wf4[r * 16 + sl], f);
            }
            acc.x = fmaf(hv.x, f.x, acc.x);
            acc.y = fmaf(hv.y, f.y, acc.y);
            acc.z = fmaf(hv.z, f.z, acc.z);
            acc.w = fmaf(hv.w, f.w, acc.w);
        }
    }
    g_agg4[(size_t)node * 16 + sl] = acc;
}

// ---------------- head: one block (128 threads) per graph ----------------
__global__ void k_head(const float* __restrict__ Wsm, const float* __restrict__ bsm,
                       const float* __restrict__ Wbg1, const float* __restrict__ bbg1,
                       const float* __restrict__ Wbg2, const float* __restrict__ bbg2,
                       const float* __restrict__ Weh1, const float* __restrict__ beh1,
                       const float* __restrict__ Weh2, const float* __restrict__ beh2,
                       float* __restrict__ out) {
    __shared__ float cs[NF];
    __shared__ float c2[2 * NH];
    __shared__ float red[128];

    int g = blockIdx.x, t = threadIdx.x;
    const float* gsum = (const float*)g_gsum4;

    if (t < NF) {
        float cnt = fmaxf(g_gcnt[g], 1.0f);
        cs[t] = gsum[(size_t)g * NF + t] / cnt;
    }
    __syncthreads();

    {
        float acc = bsm[t];
#pragma unroll 8
        for (int k = 0; k < NF; k++) acc += cs[k] * Wsm[k * 128 + t];
        c2[t] = fmaxf(acc, 0.0f);
    }
    __syncthreads();

    float partial;
    if (t < NH) {
        float acc = bbg1[t];
#pragma unroll 8
        for (int k = 0; k < 2 * NH; k++) acc += c2[k] * Wbg1[k * NH + t];
        partial = fmaxf(acc, 0.0f) * Wbg2[t];
    } else {
        int j = t - NH;
        float acc = beh1[j];
#pragma unroll 8
        for (int k = 0; k < 2 * NH; k++) acc += c2[k] * Weh1[k * NH + j];
        partial = fmaxf(acc, 0.0f) * Weh2[j];
    }
    red[t] = partial;
    __syncthreads();

    int base = t & 64;
    int l = t & 63;
#pragma unroll
    for (int s = 32; s > 0; s >>= 1) {
        if (l < s) red[base + l] += red[base + l + s];
        __syncthreads();
    }
    if (t == 0)  out[g]      = red[0]  + bbg2[0];
    if (t == 64) out[NG + g] = red[64] + beh2[0];
}

// ---------------- launch ----------------
extern "C" void kernel_launch(void* const* d_in, const int* in_sizes, int n_in,
                              void* d_out, int out_size) {
    const int*   x_ids = (const int*)d_in[0];
    const int*   eidx  = (const int*)d_in[1];
    const float* ea    = (const float*)d_in[2];
    const int*   batch = (const int*)d_in[3];
    const float* emb   = (const float*)d_in[4];
    const float* W1    = (const float*)d_in[5];
    const float* b1    = (const float*)d_in[6];
    const float* We    = (const float*)d_in[7];
    const float* be    = (const float*)d_in[8];
    const float* W2    = (const float*)d_in[9];
    const float* b2    = (const float*)d_in[10];
    const float* Wsm   = (const float*)d_in[11];
    const float* bsm   = (const float*)d_in[12];
    const float* Wbg1  = (const float*)d_in[13];
    const float* bbg1  = (const float*)d_in[14];
    const float* Wbg2  = (const float*)d_in[15];
    const float* bbg2  = (const float*)d_in[16];
    const float* Weh1  = (const float*)d_in[17];
    const float* beh1  = (const float*)d_in[18];
    const float* Weh2  = (const float*)d_in[19];
    const float* beh2  = (const float*)d_in[20];

    const int* src = eidx;
    const int* dst = eidx + NE;
    float* out = (float*)d_out;

    const int GB = (NN + 63) / 64;
    const int EB = (NN + 15) / 16;

    // CSR build (once per launch)
    k_zero<<<(NN + 255) / 256, 256>>>();
    k_hist<<<(NE + 255) / 256, 256>>>(dst);
    k_scan<<<1, 1024>>>();
    k_scatter<<<(NE + 255) / 256, 256>>>(src, dst, ea);

    for (int i = 0; i < 3; i++) {
        k_node_gemm<<<GB, 128>>>(W1 + i * NF * NF, b1 + i * NF, 0,
                                 (i == 0) ? x_ids : nullptr, (const float4*)emb, nullptr);
        k_edge_csr<<<EB, 256>>>(We + i * NRBF * NF, be + i * NF);
        k_node_gemm<<<GB, 128>>>(W2 + i * NF * NF, b2 + i * NF, (i == 2) ? 2 : 1,
                                 nullptr, nullptr, batch);
    }

    k_head<<<NG, 128>>>(Wsm, bsm, Wbg1, bbg1, Wbg2, bbg2, Weh1, beh1, Weh2, beh2, out);
}

// round 5
// speedup vs baseline: 1.5277x; 1.5277x over previous
#include <cuda_runtime.h>
#include <math.h>

#define NN   50000
#define NE   800000
#define NF   64
#define NRBF 10
#define NG   512
#define NH   64
#define NTYPE 95

// ---------------- scratch (device globals) ----------------
__device__ float4 g_x4[NN * 16];       // node features
__device__ float4 g_h4[NN * 16];       // pre-message transform
__device__ float4 g_agg4[NN * 16];     // scatter accumulator
__device__ float4 g_gsum4[NG * 16];    // per-graph sums
__device__ float  g_gcnt[NG];          // per-graph counts
__device__ float  g_hemb[NTYPE * NF];  // emb @ W1[0] + b1[0]
__device__ int    g_deg[NN];
__device__ int    g_rowptr[NN + 1];
__device__ int    g_cursor[NN];
__device__ int    g_csr_src[NE + 16];
__device__ int    g_csr_dst[NE + 16];
__device__ float  g_csr_dist[NE + 16];

// ---------------- helpers ----------------
__device__ __forceinline__ void red_add_v4(float* p, float4 v) {
    asm volatile("red.global.add.v4.f32 [%0], {%1,%2,%3,%4};"
                 :: "l"(p), "f"(v.x), "f"(v.y), "f"(v.z), "f"(v.w) : "memory");
}
__device__ __forceinline__ void red_add_f(float* p, float v) {
    asm volatile("red.global.add.f32 [%0], %1;" :: "l"(p), "f"(v) : "memory");
}
__device__ __forceinline__ unsigned long long pack2(float x, float y) {
    unsigned long long r;
    asm("mov.b64 %0, {%1,%2};" : "=l"(r) : "f"(x), "f"(y));
    return r;
}
__device__ __forceinline__ void fma2(unsigned long long& d, unsigned long long a, unsigned long long b) {
    asm("fma.rn.f32x2 %0, %1, %2, %3;" : "=l"(d) : "l"(a), "l"(b), "l"(d));
}
__device__ __forceinline__ float2 unpack2(unsigned long long v) {
    float2 f;
    asm("mov.b64 {%0,%1}, %2;" : "=f"(f.x), "=f"(f.y) : "l"(v));
    return f;
}
__device__ __forceinline__ float4 f4fma(float s, float4 w, float4 a) {
    return make_float4(fmaf(s, w.x, a.x), fmaf(s, w.y, a.y),
                       fmaf(s, w.z, a.z), fmaf(s, w.w, a.w));
}
__device__ __forceinline__ float sp(float x) {   // stable softplus
    return fmaxf(x, 0.0f) + log1pf(expf(-fabsf(x)));
}

// ---------------- CSR-sort build ----------------
__global__ void k_zero() {
    int t = blockIdx.x * blockDim.x + threadIdx.x;
    if (t < NN) g_deg[t] = 0;
    if (t < NG * 16) g_gsum4[t] = make_float4(0.f, 0.f, 0.f, 0.f);
    if (t < NG) g_gcnt[t] = 0.0f;
}
__global__ void k_hist(const int* __restrict__ dst) {
    int e = blockIdx.x * blockDim.x + threadIdx.x;
    if (e < NE) atomicAdd(&g_deg[dst[e]], 1);
}
__global__ void k_scan() {
    __shared__ int sums[1024];
    int t = threadIdx.x;
    const int CH = (NN + 1023) / 1024;
    int base = t * CH;
    int s = 0;
    for (int i = 0; i < CH; i++) {
        int idx = base + i;
        if (idx < NN) s += g_deg[idx];
    }
    sums[t] = s;
    __syncthreads();
    for (int off = 1; off < 1024; off <<= 1) {
        int v = (t >= off) ? sums[t - off] : 0;
        __syncthreads();
        sums[t] += v;
        __syncthreads();
    }
    int run = (t == 0) ? 0 : sums[t - 1];
    for (int i = 0; i < CH; i++) {
        int idx = base + i;
        if (idx < NN) {
            g_rowptr[idx] = run;
            g_cursor[idx] = run;
            run += g_deg[idx];
        }
    }
    if (t == 1023) g_rowptr[NN] = NE;
}
__global__ void k_scatter(const int* __restrict__ src, const int* __restrict__ dst,
                          const float* __restrict__ ea) {
    int e = blockIdx.x * blockDim.x + threadIdx.x;
    if (e >= NE) return;
    int d = dst[e];
    int pos = atomicAdd(&g_cursor[d], 1);
    g_csr_src[pos]  = src[e];
    g_csr_dst[pos]  = d;
    g_csr_dist[pos] = ea[e];
}

// ---------------- tiny GEMM: h_emb = emb @ W1[0] + b1[0]  (95 x 64) ----------------
__global__ void k_emb_w1(const float* __restrict__ emb, const float* __restrict__ W,
                         const float* __restrict__ b) {
    __shared__ float Ws[NF * NF];
    int t = threadIdx.x;          // 64 threads = one output col each
    for (int i = t; i < NF * NF; i += 64) Ws[i] = W[i];
    __syncthreads();
    int row = blockIdx.x;         // atom type
    float acc = b[t];
    const float* er = emb + row * NF;
#pragma unroll 8
    for (int k = 0; k < NF; k++) acc += er[k] * Ws[k * NF + t];
    g_hemb[row * NF + t] = acc;
}

// ---------------- conv0 front: x = emb[ids], h = hemb[ids], agg = 0 ----------------
__global__ void k_embed0(const int* __restrict__ ids, const float4* __restrict__ emb4) {
    int t = blockIdx.x * blockDim.x + threadIdx.x;
    if (t >= NN * 16) return;
    int n = t >> 4, c = t & 15;
    int id = ids[n];
    g_x4[t] = emb4[(size_t)id * 16 + c];
    g_h4[t] = ((const float4*)g_hemb)[(size_t)id * 16 + c];
    g_agg4[t] = make_float4(0.f, 0.f, 0.f, 0.f);
}

// ---------------- node GEMM: 64 rows/block, 128 thr, 4 rows x 8 cols/thread ----------------
// mode 0: g_h = g_x @ W + b ; zero g_agg
// mode 1: g_x = softplus(g_x + g_agg @ W + b)
// mode 2: like 1, result goes straight to graph pool
__global__ __launch_bounds__(128) void k_node_gemm(
        const float* __restrict__ W, const float* __restrict__ b, int mode,
        const int* __restrict__ batch) {
    __shared__ float4 Ws4[NF * 16];
    __shared__ float4 xs4[64 * 17];
    __shared__ float  bs[NF];

    int t = threadIdx.x;
    const float4* W4 = (const float4*)W;
#pragma unroll
    for (int i = 0; i < 8; i++) Ws4[t + 128 * i] = W4[t + 128 * i];
    if (t < NF) bs[t] = b[t];

    int rowbase = blockIdx.x * 64;
    const float4* in4 = (mode == 0) ? g_x4 : g_agg4;

#pragma unroll
    for (int i = 0; i < 8; i++) {
        int idx = t + 128 * i;
        int lr = idx >> 4, c = idx & 15;
        int row = rowbase + lr;
        if (row < NN) xs4[lr * 17 + c] = in4[(size_t)row * 16 + c];
    }
    __syncthreads();

    int cg = t & 7;
    int rl = t >> 3;

    unsigned long long a[4][4];
    {
        int cb = cg * 8;
        unsigned long long b0 = pack2(bs[cb + 0], bs[cb + 1]);
        unsigned long long b1 = pack2(bs[cb + 2], bs[cb + 3]);
        unsigned long long b2 = pack2(bs[cb + 4], bs[cb + 5]);
        unsigned long long b3 = pack2(bs[cb + 6], bs[cb + 7]);
#pragma unroll
        for (int i = 0; i < 4; i++) { a[i][0] = b0; a[i][1] = b1; a[i][2] = b2; a[i][3] = b3; }
    }

#pragma unroll 4
    for (int k4 = 0; k4 < 16; k4++) {
        float4 xv[4];
#pragma unroll
        for (int i = 0; i < 4; i++) xv[i] = xs4[(rl + 16 * i) * 17 + k4];
#pragma unroll
        for (int sub = 0; sub < 4; sub++) {
            int k = k4 * 4 + sub;
            const ulonglong2* wp = (const ulonglong2*)(Ws4 + k * 16 + cg * 2);
            ulonglong2 wA = wp[0];
            ulonglong2 wB = wp[1];
#pragma unroll
            for (int i = 0; i < 4; i++) {
                float xk = (sub == 0) ? xv[i].x : (sub == 1) ? xv[i].y : (sub == 2) ? xv[i].z : xv[i].w;
                unsigned long long s = pack2(xk, xk);
                fma2(a[i][0], s, wA.x);
                fma2(a[i][1], s, wA.y);
                fma2(a[i][2], s, wB.x);
                fma2(a[i][3], s, wB.y);
            }
        }
    }

#pragma unroll
    for (int i = 0; i < 4; i++) {
        int row = rowbase + rl + 16 * i;
        if (row >= NN) continue;
        float2 p0 = unpack2(a[i][0]), p1 = unpack2(a[i][1]);
        float2 p2 = unpack2(a[i][2]), p3 = unpack2(a[i][3]);
        float4 r0 = make_float4(p0.x, p0.y, p1.x, p1.y);
        float4 r1 = make_float4(p2.x, p2.y, p3.x, p3.y);
        size_t o = (size_t)row * 16 + cg * 2;
        if (mode == 0) {
            g_h4[o]     = r0;
            g_h4[o + 1] = r1;
            g_agg4[o]     = make_float4(0.f, 0.f, 0.f, 0.f);
            g_agg4[o + 1] = make_float4(0.f, 0.f, 0.f, 0.f);
        } else {
            float4 x0 = g_x4[o], x1 = g_x4[o + 1];
            x0 = make_float4(sp(x0.x + r0.x), sp(x0.y + r0.y), sp(x0.z + r0.z), sp(x0.w + r0.w));
            x1 = make_float4(sp(x1.x + r1.x), sp(x1.y + r1.y), sp(x1.z + r1.z), sp(x1.w + r1.w));
            if (mode == 1) {
                g_x4[o]     = x0;
                g_x4[o + 1] = x1;
            } else {
                int bg = batch[row];
                red_add_v4((float*)(g_gsum4 + (size_t)bg * 16 + cg * 2), x0);
                red_add_v4((float*)(g_gsum4 + (size_t)bg * 16 + cg * 2 + 1), x1);
                if (cg == 0) red_add_f(&g_gcnt[bg], 1.0f);
            }
        }
    }
}

// ---------------- edge kernel: dst-sorted, edge-parallel, warp-combined atomics ----------------
// 16 lanes/edge, 2 consecutive (sorted) edges per warp; if both halves share dst,
// combine messages via shfl and emit one RED.128 per lane pair.
__global__ void k_edge(const float* __restrict__ We, const float* __restrict__ be) {
    __shared__ float4 Wf4[NRBF * 16];
    __shared__ float4 bef4[16];
    int t = threadIdx.x;
    if (t < NRBF * 16) Wf4[t] = ((const float4*)We)[t];
    if (t >= NRBF * 16 && t < NRBF * 16 + 16) bef4[t - NRBF * 16] = ((const float4*)be)[t - NRBF * 16];
    __syncthreads();

    int wid = t >> 5, lane = t & 31;
    int sub = lane >> 4;
    int sl  = lane & 15;
    int e = blockIdx.x * 16 + wid * 2 + sub;
    if (e >= NE) return;

    int s    = g_csr_src[e];
    int d    = g_csr_dst[e];
    float dist = g_csr_dist[e];

    // gather early
    float4 hv = __ldg(g_h4 + (size_t)s * 16 + sl);

    float ev = 0.0f;
    if (sl < NRBF) {
        float tt = dist - 0.66666667f * (float)sl;
        ev = expf(-1.125f * tt * tt);
    }
    float4 f = bef4[sl];
#pragma unroll
    for (int r = 0; r < NRBF; r++) {
        float er = __shfl_sync(0xffffffffu, ev, (lane & 16) + r);
        f = f4fma(er, Wf4[r * 16 + sl], f);
    }

    float4 m = make_float4(hv.x * f.x, hv.y * f.y, hv.z * f.z, hv.w * f.w);

    // cross-half combine (sorted => likely same dst)
    float4 mo;
    mo.x = __shfl_xor_sync(0xffffffffu, m.x, 16);
    mo.y = __shfl_xor_sync(0xffffffffu, m.y, 16);
    mo.z = __shfl_xor_sync(0xffffffffu, m.z, 16);
    mo.w = __shfl_xor_sync(0xffffffffu, m.w, 16);
    int d_o = __shfl_xor_sync(0xffffffffu, d, 16);

    float* ap = (float*)(g_agg4 + (size_t)d * 16 + sl);
    if (d == d_o) {
        if (sub == 0) {
            m.x += mo.x; m.y += mo.y; m.z += mo.z; m.w += mo.w;
            red_add_v4(ap, m);
        }
    } else {
        red_add_v4(ap, m);
    }
}

// ---------------- head ----------------
__global__ void k_head(const float* __restrict__ Wsm, const float* __restrict__ bsm,
                       const float* __restrict__ Wbg1, const float* __restrict__ bbg1,
                       const float* __restrict__ Wbg2, const float* __restrict__ bbg2,
                       const float* __restrict__ Weh1, const float* __restrict__ beh1,
                       const float* __restrict__ Weh2, const float* __restrict__ beh2,
                       float* __restrict__ out) {
    __shared__ float cs[NF];
    __shared__ float c2[2 * NH];
    __shared__ float red[128];

    int g = blockIdx.x, t = threadIdx.x;
    const float* gsum = (const float*)g_gsum4;

    if (t < NF) {
        float cnt = fmaxf(g_gcnt[g], 1.0f);
        cs[t] = gsum[(size_t)g * NF + t] / cnt;
    }
    __syncthreads();

    {
        float acc = bsm[t];
#pragma unroll 8
        for (int k = 0; k < NF; k++) acc += cs[k] * Wsm[k * 128 + t];
        c2[t] = fmaxf(acc, 0.0f);
    }
    __syncthreads();

    float partial;
    if (t < NH) {
        float acc = bbg1[t];
#pragma unroll 8
        for (int k = 0; k < 2 * NH; k++) acc += c2[k] * Wbg1[k * NH + t];
        partial = fmaxf(acc, 0.0f) * Wbg2[t];
    } else {
        int j = t - NH;
        float acc = beh1[j];
#pragma unroll 8
        for (int k = 0; k < 2 * NH; k++) acc += c2[k] * Weh1[k * NH + j];
        partial = fmaxf(acc, 0.0f) * Weh2[j];
    }
    red[t] = partial;
    __syncthreads();

    int base = t & 64;
    int l = t & 63;
#pragma unroll
    for (int s = 32; s > 0; s >>= 1) {
        if (l < s) red[base + l] += red[base + l + s];
        __syncthreads();
    }
    if (t == 0)  out[g]      = red[0]  + bbg2[0];
    if (t == 64) out[NG + g] = red[64] + beh2[0];
}

// ---------------- launch ----------------
extern "C" void kernel_launch(void* const* d_in, const int* in_sizes, int n_in,
                              void* d_out, int out_size) {
    const int*   x_ids = (const int*)d_in[0];
    const int*   eidx  = (const int*)d_in[1];
    const float* ea    = (const float*)d_in[2];
    const int*   batch = (const int*)d_in[3];
    const float* emb   = (const float*)d_in[4];
    const float* W1    = (const float*)d_in[5];
    const float* b1    = (const float*)d_in[6];
    const float* We    = (const float*)d_in[7];
    const float* be    = (const float*)d_in[8];
    const float* W2    = (const float*)d_in[9];
    const float* b2    = (const float*)d_in[10];
    const float* Wsm   = (const float*)d_in[11];
    const float* bsm   = (const float*)d_in[12];
    const float* Wbg1  = (const float*)d_in[13];
    const float* bbg1  = (const float*)d_in[14];
    const float* Wbg2  = (const float*)d_in[15];
    const float* bbg2  = (const float*)d_in[16];
    const float* Weh1  = (const float*)d_in[17];
    const float* beh1  = (const float*)d_in[18];
    const float* Weh2  = (const float*)d_in[19];
    const float* beh2  = (const float*)d_in[20];

    const int* src = eidx;
    const int* dst = eidx + NE;
    float* out = (float*)d_out;

    const int GB = (NN + 63) / 64;

    // CSR-sort build + conv0 front (emb@W1 algebraic fold)
    k_zero<<<(NN + 255) / 256, 256>>>();
    k_hist<<<(NE + 255) / 256, 256>>>(dst);
    k_scan<<<1, 1024>>>();
    k_scatter<<<(NE + 255) / 256, 256>>>(src, dst, ea);
    k_emb_w1<<<NTYPE, 64>>>(emb, W1, b1);
    k_embed0<<<(NN * 16 + 255) / 256, 256>>>(x_ids, (const float4*)emb);

    for (int i = 0; i < 3; i++) {
        if (i > 0)
            k_node_gemm<<<GB, 128>>>(W1 + i * NF * NF, b1 + i * NF, 0, nullptr);
        k_edge<<<NE / 16, 256>>>(We + i * NRBF * NF, be + i * NF);
        k_node_gemm<<<GB, 128>>>(W2 + i * NF * NF, b2 + i * NF, (i == 2) ? 2 : 1, batch);
    }

    k_head<<<NG, 128>>>(Wsm, bsm, Wbg1, bbg1, Wbg2, bbg2, Weh1, beh1, Weh2, beh2, out);
}

// round 6
// speedup vs baseline: 1.9156x; 1.2539x over previous
#include <cuda_runtime.h>
#include <math.h>

#define NN   50000
#define NE   800000
#define NF   64
#define NRBF 10
#define NG   512
#define NH   64
#define NTYPE 95

// ---------------- scratch (device globals) ----------------
__device__ float4 g_x4[NN * 16];       // node features
__device__ float4 g_h4[NN * 16];       // pre-message transform
__device__ float4 g_agg4[NN * 16];     // scatter accumulator
__device__ float4 g_gsum4[NG * 16];    // per-graph sums
__device__ float  g_gcnt[NG];          // per-graph counts
__device__ float  g_hemb[NTYPE * NF];  // emb @ W1[0] + b1[0]

// ---------------- helpers ----------------
__device__ __forceinline__ void red_add_v4(float* p, float4 v) {
    asm volatile("red.global.add.v4.f32 [%0], {%1,%2,%3,%4};"
                 :: "l"(p), "f"(v.x), "f"(v.y), "f"(v.z), "f"(v.w) : "memory");
}
__device__ __forceinline__ void red_add_f(float* p, float v) {
    asm volatile("red.global.add.f32 [%0], %1;" :: "l"(p), "f"(v) : "memory");
}
__device__ __forceinline__ unsigned long long pack2(float x, float y) {
    unsigned long long r;
    asm("mov.b64 %0, {%1,%2};" : "=l"(r) : "f"(x), "f"(y));
    return r;
}
__device__ __forceinline__ void fma2(unsigned long long& d, unsigned long long a, unsigned long long b) {
    asm("fma.rn.f32x2 %0, %1, %2, %3;" : "=l"(d) : "l"(a), "l"(b), "l"(d));
}
__device__ __forceinline__ float2 unpack2(unsigned long long v) {
    float2 f;
    asm("mov.b64 {%0,%1}, %2;" : "=f"(f.x), "=f"(f.y) : "l"(v));
    return f;
}
__device__ __forceinline__ float4 f4fma(float s, float4 w, float4 a) {
    return make_float4(fmaf(s, w.x, a.x), fmaf(s, w.y, a.y),
                       fmaf(s, w.z, a.z), fmaf(s, w.w, a.w));
}
__device__ __forceinline__ float4 f4mul(float4 a, float4 b) {
    return make_float4(a.x * b.x, a.y * b.y, a.z * b.z, a.w * b.w);
}
__device__ __forceinline__ float sp(float x) {   // stable softplus
    return fmaxf(x, 0.0f) + log1pf(expf(-fabsf(x)));
}

// ---------------- tiny GEMM: g_hemb = emb @ W1[0] + b1[0]  (95 x 64) ----------------
__global__ void k_emb_w1(const float* __restrict__ emb, const float* __restrict__ W,
                         const float* __restrict__ b) {
    __shared__ float Ws[NF * NF];
    int t = threadIdx.x;          // 64 threads, one output col each
    for (int i = t; i < NF * NF; i += 64) Ws[i] = W[i];
    __syncthreads();
    int row = blockIdx.x;
    float acc = b[t];
    const float* er = emb + row * NF;
#pragma unroll 8
    for (int k = 0; k < NF; k++) acc += er[k] * Ws[k * NF + t];
    g_hemb[row * NF + t] = acc;
}

// ---------------- conv0 front: x = emb[ids], h = hemb[ids], agg = 0, pool zero ----------------
__global__ void k_embed0(const int* __restrict__ ids, const float4* __restrict__ emb4) {
    int t = blockIdx.x * blockDim.x + threadIdx.x;
    if (t < NG * 16) g_gsum4[t] = make_float4(0.f, 0.f, 0.f, 0.f);
    if (t < NG) g_gcnt[t] = 0.0f;
    if (t >= NN * 16) return;
    int n = t >> 4, c = t & 15;
    int id = ids[n];
    g_x4[t] = emb4[(size_t)id * 16 + c];
    g_h4[t] = ((const float4*)g_hemb)[(size_t)id * 16 + c];
    g_agg4[t] = make_float4(0.f, 0.f, 0.f, 0.f);
}

// ---------------- node GEMM: 64 rows/block, 128 thr, 4 rows x 8 cols/thread ----------------
// mode 0: g_h = g_x @ W + b ; zero g_agg
// mode 1: g_x = softplus(g_x + g_agg @ W + b)
// mode 2: like 1, result goes straight to graph pool
__global__ __launch_bounds__(128) void k_node_gemm(
        const float* __restrict__ W, const float* __restrict__ b, int mode,
        const int* __restrict__ batch) {
    __shared__ float4 Ws4[NF * 16];
    __shared__ float4 xs4[64 * 17];
    __shared__ float  bs[NF];

    int t = threadIdx.x;
    const float4* W4 = (const float4*)W;
#pragma unroll
    for (int i = 0; i < 8; i++) Ws4[t + 128 * i] = W4[t + 128 * i];
    if (t < NF) bs[t] = b[t];

    int rowbase = blockIdx.x * 64;
    const float4* in4 = (mode == 0) ? g_x4 : g_agg4;

#pragma unroll
    for (int i = 0; i < 8; i++) {
        int idx = t + 128 * i;
        int lr = idx >> 4, c = idx & 15;
        int row = rowbase + lr;
        if (row < NN) xs4[lr * 17 + c] = in4[(size_t)row * 16 + c];
    }
    __syncthreads();

    int cg = t & 7;
    int rl = t >> 3;

    unsigned long long a[4][4];
    {
        int cb = cg * 8;
        unsigned long long b0 = pack2(bs[cb + 0], bs[cb + 1]);
        unsigned long long b1 = pack2(bs[cb + 2], bs[cb + 3]);
        unsigned long long b2 = pack2(bs[cb + 4], bs[cb + 5]);
        unsigned long long b3 = pack2(bs[cb + 6], bs[cb + 7]);
#pragma unroll
        for (int i = 0; i < 4; i++) { a[i][0] = b0; a[i][1] = b1; a[i][2] = b2; a[i][3] = b3; }
    }

#pragma unroll 4
    for (int k4 = 0; k4 < 16; k4++) {
        float4 xv[4];
#pragma unroll
        for (int i = 0; i < 4; i++) xv[i] = xs4[(rl + 16 * i) * 17 + k4];
#pragma unroll
        for (int sub = 0; sub < 4; sub++) {
            int k = k4 * 4 + sub;
            const ulonglong2* wp = (const ulonglong2*)(Ws4 + k * 16 + cg * 2);
            ulonglong2 wA = wp[0];
            ulonglong2 wB = wp[1];
#pragma unroll
            for (int i = 0; i < 4; i++) {
                float xk = (sub == 0) ? xv[i].x : (sub == 1) ? xv[i].y : (sub == 2) ? xv[i].z : xv[i].w;
                unsigned long long s = pack2(xk, xk);
                fma2(a[i][0], s, wA.x);
                fma2(a[i][1], s, wA.y);
                fma2(a[i][2], s, wB.x);
                fma2(a[i][3], s, wB.y);
            }
        }
    }

#pragma unroll
    for (int i = 0; i < 4; i++) {
        int row = rowbase + rl + 16 * i;
        if (row >= NN) continue;
        float2 p0 = unpack2(a[i][0]), p1 = unpack2(a[i][1]);
        float2 p2 = unpack2(a[i][2]), p3 = unpack2(a[i][3]);
        float4 r0 = make_float4(p0.x, p0.y, p1.x, p1.y);
        float4 r1 = make_float4(p2.x, p2.y, p3.x, p3.y);
        size_t o = (size_t)row * 16 + cg * 2;
        if (mode == 0) {
            g_h4[o]     = r0;
            g_h4[o + 1] = r1;
            g_agg4[o]     = make_float4(0.f, 0.f, 0.f, 0.f);
            g_agg4[o + 1] = make_float4(0.f, 0.f, 0.f, 0.f);
        } else {
            float4 x0 = g_x4[o], x1 = g_x4[o + 1];
            x0 = make_float4(sp(x0.x + r0.x), sp(x0.y + r0.y), sp(x0.z + r0.z), sp(x0.w + r0.w));
            x1 = make_float4(sp(x1.x + r1.x), sp(x1.y + r1.y), sp(x1.z + r1.z), sp(x1.w + r1.w));
            if (mode == 1) {
                g_x4[o]     = x0;
                g_x4[o + 1] = x1;
            } else {
                int bg = batch[row];
                red_add_v4((float*)(g_gsum4 + (size_t)bg * 16 + cg * 2), x0);
                red_add_v4((float*)(g_gsum4 + (size_t)bg * 16 + cg * 2 + 1), x1);
                if (cg == 0) red_add_f(&g_gcnt[bg], 1.0f);
            }
        }
    }
}

// ---------------- edge kernel: unsorted, 16 lanes/edge, float4 per lane ----------------
__global__ void k_edge(const int* __restrict__ src, const int* __restrict__ dst,
                       const float* __restrict__ We, const float* __restrict__ be,
                       const float* __restrict__ ea) {
    __shared__ float4 Wf4[NRBF * 16];
    __shared__ float4 bef4[16];
    int t = threadIdx.x;
    if (t < NRBF * 16) Wf4[t] = ((const float4*)We)[t];
    if (t >= NRBF * 16 && t < NRBF * 16 + 16) bef4[t - NRBF * 16] = ((const float4*)be)[t - NRBF * 16];
    __syncthreads();

    int wid = t >> 5, lane = t & 31;
    int sub = lane >> 4;          // edge within warp
    int sl  = lane & 15;          // float4 slot
    int e = blockIdx.x * 16 + wid * 2 + sub;
    if (e >= NE) return;

    int s = src[e];
    int d = dst[e];
    float dist = ea[e];

    // issue the gather as early as possible
    float4 hv = __ldg(g_h4 + (size_t)s * 16 + sl);

    float ev = 0.0f;
    if (sl < NRBF) {
        float tt = dist - 0.66666667f * (float)sl;
        ev = __expf(-1.125f * tt * tt);
    }
    float4 f = bef4[sl];
#pragma unroll
    for (int r = 0; r < NRBF; r++) {
        float er = __shfl_sync(0xffffffffu, ev, (lane & 16) + r);
        f = f4fma(er, Wf4[r * 16 + sl], f);
    }

    float4 m = f4mul(hv, f);
    red_add_v4((float*)(g_agg4 + (size_t)d * 16 + sl), m);
}

// ---------------- head: one block (128 threads) per graph ----------------
__global__ void k_head(const float* __restrict__ Wsm, const float* __restrict__ bsm,
                       const float* __restrict__ Wbg1, const float* __restrict__ bbg1,
                       const float* __restrict__ Wbg2, const float* __restrict__ bbg2,
                       const float* __restrict__ Weh1, const float* __restrict__ beh1,
                       const float* __restrict__ Weh2, const float* __restrict__ beh2,
                       float* __restrict__ out) {
    __shared__ float cs[NF];
    __shared__ float c2[2 * NH];
    __shared__ float red[128];

    int g = blockIdx.x, t = threadIdx.x;
    const float* gsum = (const float*)g_gsum4;

    if (t < NF) {
        float cnt = fmaxf(g_gcnt[g], 1.0f);
        cs[t] = gsum[(size_t)g * NF + t] / cnt;
    }
    __syncthreads();

    {
        float acc = bsm[t];
#pragma unroll 8
        for (int k = 0; k < NF; k++) acc += cs[k] * Wsm[k * 128 + t];
        c2[t] = fmaxf(acc, 0.0f);
    }
    __syncthreads();

    float partial;
    if (t < NH) {
        float acc = bbg1[t];
#pragma unroll 8
        for (int k = 0; k < 2 * NH; k++) acc += c2[k] * Wbg1[k * NH + t];
        partial = fmaxf(acc, 0.0f) * Wbg2[t];
    } else {
        int j = t - NH;
        float acc = beh1[j];
#pragma unroll 8
        for (int k = 0; k < 2 * NH; k++) acc += c2[k] * Weh1[k * NH + j];
        partial = fmaxf(acc, 0.0f) * Weh2[j];
    }
    red[t] = partial;
    __syncthreads();

    int base = t & 64;
    int l = t & 63;
#pragma unroll
    for (int s = 32; s > 0; s >>= 1) {
        if (l < s) red[base + l] += red[base + l + s];
        __syncthreads();
    }
    if (t == 0)  out[g]      = red[0]  + bbg2[0];
    if (t == 64) out[NG + g] = red[64] + beh2[0];
}

// ---------------- launch ----------------
extern "C" void kernel_launch(void* const* d_in, const int* in_sizes, int n_in,
                              void* d_out, int out_size) {
    const int*   x_ids = (const int*)d_in[0];
    const int*   eidx  = (const int*)d_in[1];
    const float* ea    = (const float*)d_in[2];
    const int*   batch = (const int*)d_in[3];
    const float* emb   = (const float*)d_in[4];
    const float* W1    = (const float*)d_in[5];
    const float* b1    = (const float*)d_in[6];
    const float* We    = (const float*)d_in[7];
    const float* be    = (const float*)d_in[8];
    const float* W2    = (const float*)d_in[9];
    const float* b2    = (const float*)d_in[10];
    const float* Wsm   = (const float*)d_in[11];
    const float* bsm   = (const float*)d_in[12];
    const float* Wbg1  = (const float*)d_in[13];
    const float* bbg1  = (const float*)d_in[14];
    const float* Wbg2  = (const float*)d_in[15];
    const float* bbg2  = (const float*)d_in[16];
    const float* Weh1  = (const float*)d_in[17];
    const float* beh1  = (const float*)d_in[18];
    const float* Weh2  = (const float*)d_in[19];
    const float* beh2  = (const float*)d_in[20];

    const int* src = eidx;
    const int* dst = eidx + NE;
    float* out = (float*)d_out;

    const int GB = (NN + 63) / 64;

    k_emb_w1<<<NTYPE, 64>>>(emb, W1, b1);
    k_embed0<<<(NN * 16 + 255) / 256, 256>>>(x_ids, (const float4*)emb);

    for (int i = 0; i < 3; i++) {
        if (i > 0)
            k_node_gemm<<<GB, 128>>>(W1 + i * NF * NF, b1 + i * NF, 0, nullptr);
        k_edge<<<NE / 16, 256>>>(src, dst, We + i * NRBF * NF, be + i * NF, ea);
        k_node_gemm<<<GB, 128>>>(W2 + i * NF * NF, b2 + i * NF, (i == 2) ? 2 : 1, batch);
    }

    k_head<<<NG, 128>>>(Wsm, bsm, Wbg1, bbg1, Wbg2, bbg2, Weh1, beh1, Weh2, beh2, out);
}